// round 11
// baseline (speedup 1.0000x reference)
#include <cuda_runtime.h>
#include <cstdint>

#define FULLMASK 0xffffffffu

__device__ __forceinline__ int pidx(int i, int j) {
    const int off[4] = {0, 4, 7, 9};
    return off[i] + (j - i - 1);
}

__global__ __launch_bounds__(256, 4)
void gpf_kernel(const float* __restrict__ vtx,
                const void* __restrict__ ids_raw,
                float* __restrict__ out, int n, int ngroups)
{
    const int lane = threadIdx.x & 31;
    const int s    = lane & 7;                  // sub-lane within 8-lane group
    const int gid  = (lane >> 3) & 3;           // group 0..3 within warp
    const int wid  = threadIdx.x >> 5;          // warp 0..7 within block

    // dtype sniff once (int64 vs int32 storage of arange ids)
    const int* w32 = (const int*)ids_raw;
    const bool is64 = (__ldg(w32 + 1) == 0) && (__ldg(w32 + 3) == 0);
    const long long* w64 = (const long long*)ids_raw;

    for (int grp = blockIdx.x; grp < ngroups; grp += gridDim.x) {
        // warp covers 8 elements: A = wb+gid (lanes s<4 tail), B = wb+4+gid
        const int wb = grp * 64 + wid * 8;
        const int eA_raw = wb + gid;
        const int eB_raw = wb + 4 + gid;
        const int eA = (eA_raw < n) ? eA_raw : 0;
        const int eB = (eB_raw < n) ? eB_raw : 0;
        const bool hiHalf = (s & 4) != 0;
        const int e      = hiHalf ? eB : eA;
        const int e_raw  = hiHalf ? eB_raw : eA_raw;

        // issue the id load early so it overlaps the vertex stream
        const long long idv = is64 ? __ldg(w64 + e) : (long long)__ldg(w32 + e);

        const float* baseA = vtx + (size_t)eA * 320;
        const float* baseB = vtx + (size_t)eB * 320;

        float gA[15], gB[15];
#pragma unroll
        for (int k = 0; k < 15; k++) { gA[k] = 0.0f; gB[k] = 0.0f; }

        // lanes 0..7 of a group read one contiguous 128B row per (i,ch): full wavefronts
#pragma unroll
        for (int ch = 0; ch < 2; ch++) {
            float4 a[5];
#pragma unroll
            for (int i = 0; i < 5; i++)
                a[i] = __ldcs(reinterpret_cast<const float4*>(baseA + i * 64 + ch * 32 + s * 4));
#pragma unroll
            for (int i = 0; i < 5; i++) {
                gA[i] += a[i].x * a[i].x; gA[i] += a[i].y * a[i].y;
                gA[i] += a[i].z * a[i].z; gA[i] += a[i].w * a[i].w;
            }
            int k = 5;
#pragma unroll
            for (int i = 0; i < 5; i++)
#pragma unroll
                for (int j = i + 1; j < 5; j++) {
                    gA[k] += a[i].x * a[j].x; gA[k] += a[i].y * a[j].y;
                    gA[k] += a[i].z * a[j].z; gA[k] += a[i].w * a[j].w;
                    k++;
                }
        }
#pragma unroll
        for (int ch = 0; ch < 2; ch++) {
            float4 a[5];
#pragma unroll
            for (int i = 0; i < 5; i++)
                a[i] = __ldcs(reinterpret_cast<const float4*>(baseB + i * 64 + ch * 32 + s * 4));
#pragma unroll
            for (int i = 0; i < 5; i++) {
                gB[i] += a[i].x * a[i].x; gB[i] += a[i].y * a[i].y;
                gB[i] += a[i].z * a[i].z; gB[i] += a[i].w * a[i].w;
            }
            int k = 5;
#pragma unroll
            for (int i = 0; i < 5; i++)
#pragma unroll
                for (int j = i + 1; j < 5; j++) {
                    gB[k] += a[i].x * a[j].x; gB[k] += a[i].y * a[j].y;
                    gB[k] += a[i].z * a[j].z; gB[k] += a[i].w * a[j].w;
                    k++;
                }
        }

        // butterfly off=1,2: partial sums within 4-lane halves
#pragma unroll
        for (int off = 1; off <= 2; off <<= 1) {
#pragma unroll
            for (int k = 0; k < 15; k++) {
                gA[k] += __shfl_xor_sync(FULLMASK, gA[k], off);
                gB[k] += __shfl_xor_sync(FULLMASK, gB[k], off);
            }
        }
        // exchange at off=4: lanes s<4 end with full gA, lanes s>=4 with full gB
        float g[15];
#pragma unroll
        for (int k = 0; k < 15; k++) {
            float send = hiHalf ? gA[k] : gB[k];
            float recv = __shfl_xor_sync(FULLMASK, send, 4);
            g[k] = (hiHalf ? gB[k] : gA[k]) + recv;
        }

        // ---------------- scalar tail: SIMD across 8 elements per warp ----------------
        auto dotf = [&](int i, int j) -> float {
            if (i == j) return g[i];
            int lo = i < j ? i : j, hi = i < j ? j : i;
            return g[5 + pidx(lo, hi)];
        };

        float edges[10];
        {
            int k = 0;
#pragma unroll
            for (int i = 0; i < 5; i++)
#pragma unroll
                for (int j = i + 1; j < 5; j++) {
                    float d2 = fmaxf(g[i] + g[j] - 2.0f * g[5 + k], 0.0f);
                    edges[k] = sqrtf(d2);
                    k++;
                }
        }
        float esum = 0.0f;
#pragma unroll
        for (int k = 0; k < 10; k++) esum += edges[k];
        float mean_edge = esum * 0.1f;
        float evar = 0.0f;
#pragma unroll
        for (int k = 0; k < 10; k++) { float d = edges[k] - mean_edge; evar += d * d; }
        float std_edge = sqrtf(evar * (1.0f / 9.0f));   // ddof=1

        float S[5];
#pragma unroll
        for (int i = 0; i < 5; i++) {
            float si = 0.0f;
#pragma unroll
            for (int j = 0; j < 5; j++) si += dotf(i, j);
            S[i] = si;
        }
        float T = S[0] + S[1] + S[2] + S[3] + S[4];
        float dsum = 0.0f, dists[5];
#pragma unroll
        for (int i = 0; i < 5; i++) {
            float c = g[i] - 0.4f * S[i] + T * (1.0f / 25.0f);
            dists[i] = sqrtf(fmaxf(c, 0.0f));
            dsum += dists[i];
        }
        float dmean = dsum * 0.2f;
        float dvar = 0.0f;
#pragma unroll
        for (int k = 0; k < 5; k++) { float d = dists[k] - dmean; dvar += d * d; }
        float spread = sqrtf(dvar * 0.25f);

        // 4-simplex volume via edge-vector Gram cofactor expansion (detE = 576 V^2)
        float E00 = dotf(1,1) - 2.0f*dotf(0,1) + g[0];
        float E11 = dotf(2,2) - 2.0f*dotf(0,2) + g[0];
        float E22 = dotf(3,3) - 2.0f*dotf(0,3) + g[0];
        float E33 = dotf(4,4) - 2.0f*dotf(0,4) + g[0];
        float E01 = dotf(1,2) - dotf(0,1) - dotf(0,2) + g[0];
        float E02 = dotf(1,3) - dotf(0,1) - dotf(0,3) + g[0];
        float E03 = dotf(1,4) - dotf(0,1) - dotf(0,4) + g[0];
        float E12 = dotf(2,3) - dotf(0,2) - dotf(0,3) + g[0];
        float E13 = dotf(2,4) - dotf(0,2) - dotf(0,4) + g[0];
        float E23 = dotf(3,4) - dotf(0,3) - dotf(0,4) + g[0];

        float S01 = E00*E11 - E01*E01;
        float S02 = E00*E12 - E01*E02;
        float S03 = E00*E13 - E01*E03;
        float S12 = E01*E12 - E11*E02;
        float S13 = E01*E13 - E11*E03;
        float S23 = E02*E13 - E12*E03;
        float C01 = E02*E13 - E12*E03;
        float C02 = E02*E23 - E22*E03;
        float C03 = E02*E33 - E23*E03;
        float C12 = E12*E23 - E22*E13;
        float C13 = E12*E33 - E23*E13;
        float C23 = E22*E33 - E23*E23;

        float det = S01*C23 - S02*C13 + S03*C12 + S12*C03 - S13*C02 + S23*C01;
        float vol = sqrtf(fmaxf(det, 0.0f) * (1.0f / 576.0f));

        float volume_norm = 1.0f / (1.0f + __expf(-(vol * 10.0f)));
        float edge_ratio  = 1.0f / (1.0f + __expf(-(std_edge / (mean_edge + 1e-6f))));
        float spread_norm = 1.0f / (1.0f + __expf(-spread));

        float sg = __fadd_rn(__fadd_rn(__fmul_rn(volume_norm, 0.4f),
                                       __fmul_rn(edge_ratio, 0.3f)),
                             __fmul_rn(spread_norm, 0.3f));

        long long h = (idv * 2654435761LL) % 1000000LL;
        float idc = __fdiv_rn((float)h, 1000000.0f);

        float seed = __fadd_rn(__fmul_rn(0.1f, sg), __fmul_rn(0.9f, idc));
        seed = fminf(fmaxf(seed, 1e-6f), (float)(1.0 - 1e-6));

        // Cantor digit extraction, depth 8
        float x = seed, cantor = 0.0f, factor = 0.5f;
#pragma unroll
        for (int it = 0; it < 8; it++) {
            float xs = __fmul_rn(x, 3.0f);
            int dg = (int)xs;                 // trunc, x >= 0
            x = __fsub_rn(xs, (float)dg);
            cantor = __fadd_rn(cantor, (dg == 2) ? factor : 0.0f);
            factor *= 0.5f;
        }
        float result = fminf(fmaxf(cantor, 0.0f), 1.0f);

        if ((s & 3) == 0 && e_raw < n)
            out[e_raw] = result;
    }
}

extern "C" void kernel_launch(void* const* d_in, const int* in_sizes, int n_in,
                              void* d_out, int out_size) {
    const float* vtx = (const float*)d_in[0];
    const void* ids = d_in[1];
    float* out = (float*)d_out;
    int n = in_sizes[1];                  // B
    int threads = 256;
    int ngroups = (n + 63) / 64;          // 64 elements per block-iteration
    int maxres = 148 * 4;                 // persistent: one wave of resident blocks
    int blocks = ngroups < maxres ? ngroups : maxres;
    gpf_kernel<<<blocks, threads>>>(vtx, ids, out, n, ngroups);
}

// round 12
// speedup vs baseline: 1.0491x; 1.0491x over previous
#include <cuda_runtime.h>
#include <cstdint>

#define FULLMASK 0xffffffffu

// pair index for (i,j), i<j, triu order (0,1)(0,2)(0,3)(0,4)(1,2)(1,3)(1,4)(2,3)(2,4)(3,4)
__device__ __forceinline__ int pidx(int i, int j) {
    const int off[4] = {0, 4, 7, 9};
    return off[i] + (j - i - 1);
}

__global__ __launch_bounds__(256, 4)
void gpf_kernel(const float* __restrict__ vtx,
                const void* __restrict__ ids_raw,
                float* __restrict__ out, int n, int ngroups)
{
    const int lane = threadIdx.x & 31;
    const int s    = lane & 7;            // sub-lane within 8-lane group
    const int gid  = (threadIdx.x & 31) >> 3;   // group 0..3 within warp
    const int wid  = threadIdx.x >> 5;    // warp 0..7 within block

    // dtype sniff once (int64 vs int32 storage of arange ids)
    const int* w32 = (const int*)ids_raw;
    const bool is64 = (__ldg(w32 + 1) == 0) && (__ldg(w32 + 3) == 0);

    for (int grp = blockIdx.x; grp < ngroups; grp += gridDim.x) {
        // warp covers 8 elements: A = base+gid (lanes s<4 tail), B = base+4+gid
        const int wb = grp * 64 + wid * 8;
        const int eA_raw = wb + gid;
        const int eB_raw = wb + 4 + gid;
        const int eA = (eA_raw < n) ? eA_raw : 0;
        const int eB = (eB_raw < n) ? eB_raw : 0;

        const float* baseA = vtx + (size_t)eA * 320;
        const float* baseB = vtx + (size_t)eB * 320;

        float gA[15], gB[15];
#pragma unroll
        for (int k = 0; k < 15; k++) { gA[k] = 0.0f; gB[k] = 0.0f; }

        // lanes 0..7 of a group read one contiguous 128B row per (i,ch): full wavefronts
#pragma unroll
        for (int ch = 0; ch < 2; ch++) {
            float4 a[5];
#pragma unroll
            for (int i = 0; i < 5; i++)
                a[i] = __ldcs(reinterpret_cast<const float4*>(baseA + i * 64 + ch * 32 + s * 4));
#pragma unroll
            for (int i = 0; i < 5; i++) {
                gA[i] += a[i].x * a[i].x;
                gA[i] += a[i].y * a[i].y;
                gA[i] += a[i].z * a[i].z;
                gA[i] += a[i].w * a[i].w;
            }
            int k = 5;
#pragma unroll
            for (int i = 0; i < 5; i++)
#pragma unroll
                for (int j = i + 1; j < 5; j++) {
                    gA[k] += a[i].x * a[j].x;
                    gA[k] += a[i].y * a[j].y;
                    gA[k] += a[i].z * a[j].z;
                    gA[k] += a[i].w * a[j].w;
                    k++;
                }
        }
#pragma unroll
        for (int ch = 0; ch < 2; ch++) {
            float4 a[5];
#pragma unroll
            for (int i = 0; i < 5; i++)
                a[i] = __ldcs(reinterpret_cast<const float4*>(baseB + i * 64 + ch * 32 + s * 4));
#pragma unroll
            for (int i = 0; i < 5; i++) {
                gB[i] += a[i].x * a[i].x;
                gB[i] += a[i].y * a[i].y;
                gB[i] += a[i].z * a[i].z;
                gB[i] += a[i].w * a[i].w;
            }
            int k = 5;
#pragma unroll
            for (int i = 0; i < 5; i++)
#pragma unroll
                for (int j = i + 1; j < 5; j++) {
                    gB[k] += a[i].x * a[j].x;
                    gB[k] += a[i].y * a[j].y;
                    gB[k] += a[i].z * a[j].z;
                    gB[k] += a[i].w * a[j].w;
                    k++;
                }
        }

        // butterfly off=1,2: lanes 0-3 hold sums over s0-3, lanes 4-7 over s4-7
#pragma unroll
        for (int off = 1; off <= 2; off <<= 1) {
#pragma unroll
            for (int k = 0; k < 15; k++) {
                gA[k] += __shfl_xor_sync(FULLMASK, gA[k], off);
                gB[k] += __shfl_xor_sync(FULLMASK, gB[k], off);
            }
        }
        // exchange step at off=4: lanes s<4 end with full gA, lanes s>=4 with full gB
        float g[15];
        const bool hiHalf = (s & 4) != 0;
#pragma unroll
        for (int k = 0; k < 15; k++) {
            float send = hiHalf ? gA[k] : gB[k];
            float recv = __shfl_xor_sync(FULLMASK, send, 4);
            g[k] = (hiHalf ? gB[k] : gA[k]) + recv;
        }

        // ---------------- scalar tail: SIMD across 8 elements per warp ----------------
        const int e      = hiHalf ? eB : eA;
        const int e_raw  = hiHalf ? eB_raw : eA_raw;

        auto dotf = [&](int i, int j) -> float {
            if (i == j) return g[i];
            int lo = i < j ? i : j, hi = i < j ? j : i;
            return g[5 + pidx(lo, hi)];
        };

        float edges[10];
        {
            int k = 0;
#pragma unroll
            for (int i = 0; i < 5; i++)
#pragma unroll
                for (int j = i + 1; j < 5; j++) {
                    float d2 = fmaxf(g[i] + g[j] - 2.0f * g[5 + k], 0.0f);
                    edges[k] = sqrtf(d2);
                    k++;
                }
        }
        float esum = 0.0f;
#pragma unroll
        for (int k = 0; k < 10; k++) esum += edges[k];
        float mean_edge = esum * 0.1f;
        float evar = 0.0f;
#pragma unroll
        for (int k = 0; k < 10; k++) {
            float d = edges[k] - mean_edge;
            evar += d * d;
        }
        float std_edge = sqrtf(evar * (1.0f / 9.0f));   // ddof=1

        float S[5];
#pragma unroll
        for (int i = 0; i < 5; i++) {
            float si = 0.0f;
#pragma unroll
            for (int j = 0; j < 5; j++) si += dotf(i, j);
            S[i] = si;
        }
        float T = S[0] + S[1] + S[2] + S[3] + S[4];
        float dsum = 0.0f;
        float dists[5];
#pragma unroll
        for (int i = 0; i < 5; i++) {
            float c = g[i] - 0.4f * S[i] + T * (1.0f / 25.0f);
            dists[i] = sqrtf(fmaxf(c, 0.0f));
            dsum += dists[i];
        }
        float dmean = dsum * 0.2f;
        float dvar = 0.0f;
#pragma unroll
        for (int k = 0; k < 5; k++) {
            float d = dists[k] - dmean;
            dvar += d * d;
        }
        float spread = sqrtf(dvar * 0.25f);

        // 4-simplex volume via edge-vector Gram cofactor expansion (detE = 576 V^2)
        float E00 = dotf(1,1) - 2.0f*dotf(0,1) + g[0];
        float E11 = dotf(2,2) - 2.0f*dotf(0,2) + g[0];
        float E22 = dotf(3,3) - 2.0f*dotf(0,3) + g[0];
        float E33 = dotf(4,4) - 2.0f*dotf(0,4) + g[0];
        float E01 = dotf(1,2) - dotf(0,1) - dotf(0,2) + g[0];
        float E02 = dotf(1,3) - dotf(0,1) - dotf(0,3) + g[0];
        float E03 = dotf(1,4) - dotf(0,1) - dotf(0,4) + g[0];
        float E12 = dotf(2,3) - dotf(0,2) - dotf(0,3) + g[0];
        float E13 = dotf(2,4) - dotf(0,2) - dotf(0,4) + g[0];
        float E23 = dotf(3,4) - dotf(0,3) - dotf(0,4) + g[0];

        float S01 = E00*E11 - E01*E01;
        float S02 = E00*E12 - E01*E02;
        float S03 = E00*E13 - E01*E03;
        float S12 = E01*E12 - E11*E02;
        float S13 = E01*E13 - E11*E03;
        float S23 = E02*E13 - E12*E03;
        float C01 = E02*E13 - E12*E03;
        float C02 = E02*E23 - E22*E03;
        float C03 = E02*E33 - E23*E03;
        float C12 = E12*E23 - E22*E13;
        float C13 = E12*E33 - E23*E13;
        float C23 = E22*E33 - E23*E23;

        float det = S01*C23 - S02*C13 + S03*C12 + S12*C03 - S13*C02 + S23*C01;
        float vol = sqrtf(fmaxf(det, 0.0f) * (1.0f / 576.0f));

        float volume_norm = 1.0f / (1.0f + __expf(-(vol * 10.0f)));
        float edge_ratio  = 1.0f / (1.0f + __expf(-(std_edge / (mean_edge + 1e-6f))));
        float spread_norm = 1.0f / (1.0f + __expf(-spread));

        float sg = __fadd_rn(__fadd_rn(__fmul_rn(volume_norm, 0.4f),
                                       __fmul_rn(edge_ratio, 0.3f)),
                             __fmul_rn(spread_norm, 0.3f));

        long long idv = is64 ? ((const long long*)ids_raw)[e]
                             : (long long)w32[e];
        long long h = (idv * 2654435761LL) % 1000000LL;
        float idc = __fdiv_rn((float)h, 1000000.0f);

        float seed = __fadd_rn(__fmul_rn(0.1f, sg), __fmul_rn(0.9f, idc));
        seed = fminf(fmaxf(seed, 1e-6f), (float)(1.0 - 1e-6));

        // Cantor digit extraction, depth 8
        float x = seed;
        float cantor = 0.0f;
        float factor = 0.5f;
#pragma unroll
        for (int it = 0; it < 8; it++) {
            float xs = __fmul_rn(x, 3.0f);
            int dg = (int)xs;                 // trunc, x >= 0
            x = __fsub_rn(xs, (float)dg);
            cantor = __fadd_rn(cantor, (dg == 2) ? factor : 0.0f);
            factor *= 0.5f;
        }
        float result = fminf(fmaxf(cantor, 0.0f), 1.0f);

        if ((s & 3) == 0 && e_raw < n)
            out[e_raw] = result;
    }
}

extern "C" void kernel_launch(void* const* d_in, const int* in_sizes, int n_in,
                              void* d_out, int out_size) {
    const float* vtx = (const float*)d_in[0];
    const void* ids = d_in[1];
    float* out = (float*)d_out;
    int n = in_sizes[1];                  // B
    int threads = 256;
    int ngroups = (n + 63) / 64;          // 64 elements per block-iteration
    int maxres = 148 * 4;                 // persistent: one wave of resident blocks
    int blocks = ngroups < maxres ? ngroups : maxres;
    gpf_kernel<<<blocks, threads>>>(vtx, ids, out, n, ngroups);
}